// round 10
// baseline (speedup 1.0000x reference)
#include <cuda_runtime.h>

// GraphSAGE 2-layer, N=100000, E=1600000, dims 32 -> 64 -> 32.
// Atomic-free float path: per-call CSR build (dst-indexed) + gather aggregation.
//   B0: zero degree counters (padded)
//   B1: count   deg[dst]++                          (int atomics)
//   B2: scanA   partial[c] = sum(deg chunk c)       (98 blocks)
//   B3: scanB   exclusive scan of partials          (1 block)
//   B4: scanC   per-chunk block scan -> off, cur
//   B5: fill    adj[cur[dst]++] = src
//   K1: gather  g_agg[i] = sum_{j in adj[i]} x[j]   (warp/node, shfl-staged idx)
//   K2: fused MLP (thread/node, FFMA2)
//   K3: gather  out[i] += sum_{j in adj[i]} g[j]
// Layer-2 projection applied BEFORE aggregation (linear commutes with sum).
// edge_index is int32 on device.

#define NN 100000
#define EE 1600000
#define D 32
#define CHUNK 1024
#define NB ((NN + CHUNK - 1) / CHUNK)        // 98
#define NPAD (NB * CHUNK)                    // 100352

typedef unsigned long long ull;

__device__ int   g_deg[NPAD];
__device__ int   g_part[128];
__device__ int   g_off[NN + 1];
__device__ int   g_cur[NN];
__device__ int   g_adj[EE];
__device__ float g_agg[NN * D];
__device__ float g_g[NN * D];

__device__ __forceinline__ ull fma2(ull a, ull b, ull c) {
    ull d;
    asm("fma.rn.f32x2 %0, %1, %2, %3;" : "=l"(d) : "l"(a), "l"(b), "l"(c));
    return d;
}
__device__ __forceinline__ ull pack2(float lo, float hi) {
    ull d;
    asm("mov.b64 %0, {%1, %2};" : "=l"(d) : "f"(lo), "f"(hi));
    return d;
}
__device__ __forceinline__ void unpack2(ull v, float& lo, float& hi) {
    asm("mov.b64 {%0, %1}, %2;" : "=f"(lo), "=f"(hi) : "l"(v));
}

// ---------------------------------------------------------------------------
__global__ void zero_deg_kernel() {
    int i = blockIdx.x * blockDim.x + threadIdx.x;
    if (i < NPAD / 4) ((int4*)g_deg)[i] = make_int4(0, 0, 0, 0);
}

__global__ void count_kernel(const int* __restrict__ dst, int E) {
    int e = blockIdx.x * blockDim.x + threadIdx.x;
    if (e < E) atomicAdd(&g_deg[dst[e]], 1);
}

// scanA: per-chunk total. grid=NB, block=256 (each thread sums 4 via int4).
__global__ void scanA_kernel() {
    __shared__ int ws[8];
    int c = blockIdx.x, t = threadIdx.x;
    int4 v = ((const int4*)g_deg)[c * 256 + t];
    int s = v.x + v.y + v.z + v.w;
    #pragma unroll
    for (int o = 16; o; o >>= 1) s += __shfl_xor_sync(0xffffffffu, s, o);
    if ((t & 31) == 0) ws[t >> 5] = s;
    __syncthreads();
    if (t == 0) {
        int tot = 0;
        #pragma unroll
        for (int i = 0; i < 8; i++) tot += ws[i];
        g_part[c] = tot;
    }
}

// scanB: exclusive scan of NB partials. 1 block, 128 threads.
__global__ void scanB_kernel() {
    __shared__ int ws[4];
    int t = threadIdx.x;
    int v = (t < NB) ? g_part[t] : 0;
    int lane = t & 31, w = t >> 5;
    int incl = v;
    #pragma unroll
    for (int o = 1; o < 32; o <<= 1) {
        int n = __shfl_up_sync(0xffffffffu, incl, o);
        if (lane >= o) incl += n;
    }
    if (lane == 31) ws[w] = incl;
    __syncthreads();
    int add = 0;
    for (int i = 0; i < w; i++) add += ws[i];
    if (t < NB) g_part[t] = incl - v + add;    // exclusive prefix
}

// scanC: per-chunk exclusive scan + chunk base -> g_off, g_cur.
__global__ void scanC_kernel(int E) {
    __shared__ int ws[8];
    int c = blockIdx.x, t = threadIdx.x;
    int base = c * CHUNK + t * 4;
    int4 v = ((const int4*)g_deg)[c * 256 + t];
    int tsum = v.x + v.y + v.z + v.w;
    int lane = t & 31, w = t >> 5;
    int incl = tsum;
    #pragma unroll
    for (int o = 1; o < 32; o <<= 1) {
        int n = __shfl_up_sync(0xffffffffu, incl, o);
        if (lane >= o) incl += n;
    }
    if (lane == 31) ws[w] = incl;
    __syncthreads();
    if (w == 0) {
        int x = (lane < 8) ? ws[lane] : 0;
        #pragma unroll
        for (int o = 1; o < 8; o <<= 1) {
            int n = __shfl_up_sync(0xffffffffu, x, o);
            if (lane >= o) x += n;
        }
        if (lane < 8) ws[lane] = x;              // inclusive warp-sum scan
    }
    __syncthreads();
    int excl = incl - tsum + (w > 0 ? ws[w - 1] : 0) + g_part[c];
    int o0 = excl, o1 = o0 + v.x, o2 = o1 + v.y, o3 = o2 + v.z;
    if (base < NN)     { g_off[base]     = o0; g_cur[base]     = o0; }
    if (base + 1 < NN) { g_off[base + 1] = o1; g_cur[base + 1] = o1; }
    if (base + 2 < NN) { g_off[base + 2] = o2; g_cur[base + 2] = o2; }
    if (base + 3 < NN) { g_off[base + 3] = o3; g_cur[base + 3] = o3; }
    if (c == 0 && t == 0) g_off[NN] = E;
}

__global__ void fill_kernel(const int* __restrict__ src,
                            const int* __restrict__ dst, int E) {
    int e = blockIdx.x * blockDim.x + threadIdx.x;
    if (e >= E) return;
    int pos = atomicAdd(&g_cur[dst[e]], 1);
    g_adj[pos] = src[e];
}

// ---------------------------------------------------------------------------
// Warp per node; lane = feature. Indices pre-staged 32-at-a-time via one
// coalesced load + shuffles, so all row loads are independent (MLP = deg).
__global__ void gather_x_kernel(const float* __restrict__ x, int N) {
    int lane = threadIdx.x & 31;
    int node = (blockIdx.x * blockDim.x + threadIdx.x) >> 5;
    if (node >= N) return;
    int j0 = g_off[node];
    int j1 = g_off[node + 1];
    float acc = 0.0f;
    for (int base = j0; base < j1; base += 32) {
        int idx = (base + lane < j1) ? __ldg(&g_adj[base + lane]) : 0;
        int cnt = min(32, j1 - base);
        #pragma unroll 4
        for (int k = 0; k < cnt; k++) {
            int s = __shfl_sync(0xffffffffu, idx, k);
            acc += __ldg(&x[s * D + lane]);
        }
    }
    g_agg[node * D + lane] = acc;
}

__global__ void gather_g_kernel(float* __restrict__ out, int N) {
    int lane = threadIdx.x & 31;
    int node = (blockIdx.x * blockDim.x + threadIdx.x) >> 5;
    if (node >= N) return;
    int j0 = g_off[node];
    int j1 = g_off[node + 1];
    float acc = 0.0f;
    for (int base = j0; base < j1; base += 32) {
        int idx = (base + lane < j1) ? __ldg(&g_adj[base + lane]) : 0;
        int cnt = min(32, j1 - base);
        #pragma unroll 4
        for (int k = 0; k < cnt; k++) {
            int s = __shfl_sync(0xffffffffu, idx, k);
            acc += __ldg(&g_g[s * D + lane]);
        }
    }
    out[node * D + lane] += acc;   // MLP already stored the lin_r part
}

// ---------------------------------------------------------------------------
// Thread-per-node MLP with f32x2 packed FMA (unchanged from R6).
__global__ void __launch_bounds__(128)
fused_mlp_kernel(const float* __restrict__ x,
                 const float* __restrict__ Wli,  // [64,32]
                 const float* __restrict__ bli,  // [64]
                 const float* __restrict__ Wri,  // [64,32]
                 const float* __restrict__ Wlo,  // [32,64]
                 const float* __restrict__ blo,  // [32]
                 const float* __restrict__ Wro,  // [32,64]
                 float* __restrict__ out,
                 int N) {
    __shared__ longlong2 w1l[32][16];
    __shared__ longlong2 w1r[32][16];
    __shared__ longlong2 w2l[64][8];
    __shared__ longlong2 w2r[64][8];
    __shared__ ull b1p[32];
    __shared__ ull b2p[16];

    int tid = threadIdx.x;
    {
        float* W1L = (float*)w1l;
        float* W1R = (float*)w1r;
        float* W2L = (float*)w2l;
        float* W2R = (float*)w2r;
        for (int idx = tid; idx < 2048; idx += 128) {
            int k = idx >> 6, m = idx & 63;
            W1L[k * 64 + m] = Wli[m * 32 + k];
            W1R[k * 64 + m] = Wri[m * 32 + k];
            int mm = idx >> 5, o = idx & 31;
            W2L[mm * 32 + o] = Wlo[o * 64 + mm];
            W2R[mm * 32 + o] = Wro[o * 64 + mm];
        }
        if (tid < 64) ((float*)b1p)[tid] = bli[tid];
        if (tid < 32) ((float*)b2p)[tid] = blo[tid];
    }
    __syncthreads();

    int node = blockIdx.x * 128 + tid;
    if (node >= N) return;

    float a[32], xv[32];
    {
        const float4* ar = (const float4*)&g_agg[node * D];
        const float4* xr = (const float4*)&x[node * D];
        #pragma unroll
        for (int i = 0; i < 8; i++) {
            float4 t0 = ar[i];
            a[4 * i] = t0.x; a[4 * i + 1] = t0.y; a[4 * i + 2] = t0.z; a[4 * i + 3] = t0.w;
            float4 t1 = xr[i];
            xv[4 * i] = t1.x; xv[4 * i + 1] = t1.y; xv[4 * i + 2] = t1.z; xv[4 * i + 3] = t1.w;
        }
    }

    ull h2[32];
    #pragma unroll
    for (int m2 = 0; m2 < 32; m2++) h2[m2] = b1p[m2];

    #pragma unroll
    for (int k = 0; k < 32; k++) {
        ull av2 = pack2(a[k], a[k]);
        ull xx2 = pack2(xv[k], xv[k]);
        #pragma unroll
        for (int q = 0; q < 16; q++) {
            longlong2 wl = w1l[k][q];
            longlong2 wr = w1r[k][q];
            h2[2 * q]     = fma2((ull)wl.x, av2, h2[2 * q]);
            h2[2 * q + 1] = fma2((ull)wl.y, av2, h2[2 * q + 1]);
            h2[2 * q]     = fma2((ull)wr.x, xx2, h2[2 * q]);
            h2[2 * q + 1] = fma2((ull)wr.y, xx2, h2[2 * q + 1]);
        }
    }

    float hs[64];
    #pragma unroll
    for (int m2 = 0; m2 < 32; m2++) {
        float lo, hi;
        unpack2(h2[m2], lo, hi);
        hs[2 * m2]     = fmaxf(lo, 0.0f);
        hs[2 * m2 + 1] = fmaxf(hi, 0.0f);
    }

    ull g2[16], r2[16];
    #pragma unroll
    for (int o2 = 0; o2 < 16; o2++) { g2[o2] = 0ull; r2[o2] = b2p[o2]; }

    #pragma unroll
    for (int m = 0; m < 64; m++) {
        ull hv2 = pack2(hs[m], hs[m]);
        #pragma unroll
        for (int q = 0; q < 8; q++) {
            longlong2 wl = w2l[m][q];
            longlong2 wr = w2r[m][q];
            g2[2 * q]     = fma2((ull)wl.x, hv2, g2[2 * q]);
            g2[2 * q + 1] = fma2((ull)wl.y, hv2, g2[2 * q + 1]);
            r2[2 * q]     = fma2((ull)wr.x, hv2, r2[2 * q]);
            r2[2 * q + 1] = fma2((ull)wr.y, hv2, r2[2 * q + 1]);
        }
    }

    ull* gg = (ull*)&g_g[node * D];
    ull* oo = (ull*)&out[node * D];
    #pragma unroll
    for (int o2 = 0; o2 < 16; o2++) {
        gg[o2] = g2[o2];
        oo[o2] = r2[o2];
    }
}

// ---------------------------------------------------------------------------
extern "C" void kernel_launch(void* const* d_in, const int* in_sizes, int n_in,
                              void* d_out, int out_size) {
    const float* x   = (const float*)d_in[0];
    const int*   ei  = (const int*)d_in[1];
    const float* Wli = (const float*)d_in[2];
    const float* bli = (const float*)d_in[3];
    const float* Wri = (const float*)d_in[4];
    const float* Wlo = (const float*)d_in[5];
    const float* blo = (const float*)d_in[6];
    const float* Wro = (const float*)d_in[7];
    float* out = (float*)d_out;

    int N = in_sizes[0] / D;      // 100000
    int E = in_sizes[1] / 2;      // 1600000
    const int* src = ei;
    const int* dst = ei + E;

    // CSR build (per call)
    zero_deg_kernel<<<(NPAD / 4 + 255) / 256, 256>>>();
    count_kernel<<<(E + 255) / 256, 256>>>(dst, E);
    scanA_kernel<<<NB, 256>>>();
    scanB_kernel<<<1, 128>>>();
    scanC_kernel<<<NB, 256>>>(E);
    fill_kernel<<<(E + 255) / 256, 256>>>(src, dst, E);

    // Layer 1 gather, fused MLP, layer 2 gather
    gather_x_kernel<<<(N * 32 + 255) / 256, 256>>>(x, N);
    fused_mlp_kernel<<<(N + 127) / 128, 128>>>(x, Wli, bli, Wri, Wlo, blo, Wro, out, N);
    gather_g_kernel<<<(N * 32 + 255) / 256, 256>>>(out, N);
}